// round 5
// baseline (speedup 1.0000x reference)
#include <cuda_runtime.h>
#include <cuda_bf16.h>
#include <cstdint>

#define THREADS   256
#define TM        64
#define F_DIM     128
#define K_NEIGH   16
#define O_DIM     128
#define KD        256
#define NEG_SLOPE 0.2f
#define LN_EPS    1e-5f

// smem layout (bytes). A rows padded to 264 halves (528B), W rows to 136 halves (272B).
#define A_STRIDE_H 264
#define W_STRIDE_H 136
#define OFF_A_HI   0                         // 64*528  = 33792
#define OFF_A_LO   33792                     // 33792
#define OFF_W      67584                     // 128*272 = 34816 (single buffer, restaged)
#define OFF_ADJ    102400                    // 64*16*4 = 4096
#define OFF_INV    106496                    // 256
#define OFF_BIAS   106752                    // 512
#define OFF_GAM    107264                    // 512
#define OFF_BET    107776                    // 512
#define SMEM_BYTES 108288
#define OFF_H      0                         // h tile reuses A_HI: 64*129*4 = 33024
#define H_STRIDE   129

// pre-split W in device scratch (bf16 hi/lo, row-major [O][KD])
__device__ __nv_bfloat16 g_Whi[O_DIM * KD];
__device__ __nv_bfloat16 g_Wlo[O_DIM * KD];

__device__ __forceinline__ uint32_t smem_u32(const void* p) {
    uint32_t a;
    asm("{ .reg .u64 t; cvta.to.shared.u64 t, %1; cvt.u32.u64 %0, t; }" : "=r"(a) : "l"(p));
    return a;
}
__device__ __forceinline__ void ldsm4(uint32_t* r, uint32_t addr) {
    asm volatile("ldmatrix.sync.aligned.m8n8.x4.shared.b16 {%0,%1,%2,%3}, [%4];"
        : "=r"(r[0]), "=r"(r[1]), "=r"(r[2]), "=r"(r[3]) : "r"(addr));
}
__device__ __forceinline__ void mma_bf16(float* c, const uint32_t* a, const uint32_t* b) {
    asm volatile("mma.sync.aligned.m16n8k16.row.col.f32.bf16.bf16.f32 "
        "{%0,%1,%2,%3}, {%4,%5,%6,%7}, {%8,%9}, {%0,%1,%2,%3};"
        : "+f"(c[0]), "+f"(c[1]), "+f"(c[2]), "+f"(c[3])
        : "r"(a[0]), "r"(a[1]), "r"(a[2]), "r"(a[3]), "r"(b[0]), "r"(b[1]));
}
__device__ __forceinline__ uint32_t pk2(float a, float b) {
    __nv_bfloat162 t = __floats2bfloat162_rn(a, b);
    return *reinterpret_cast<uint32_t*>(&t);
}
__device__ __forceinline__ void split1(float v, float& h, float& l) {
    h = __bfloat162float(__float2bfloat16_rn(v));
    l = v - h;
}

// ---------- prep: split W into bf16 hi/lo ----------
__global__ void prep_w_kernel(const float* __restrict__ W) {
    int i = blockIdx.x * blockDim.x + threadIdx.x;
    if (i < O_DIM * KD) {
        float v = W[i];
        __nv_bfloat16 h = __float2bfloat16_rn(v);
        g_Whi[i] = h;
        g_Wlo[i] = __float2bfloat16_rn(v - __bfloat162float(h));
    }
}

// ---------- main fused kernel ----------
__global__ void __launch_bounds__(THREADS, 2)
gnn_mma_kernel(const float* __restrict__ X,
               const int* __restrict__ adj,
               const float* __restrict__ bias,
               const float* __restrict__ gamma,
               const float* __restrict__ beta,
               float* __restrict__ out,
               int N)
{
    extern __shared__ __align__(16) char sp[];
    const uint32_t sbase = smem_u32(sp);

    int*   sAdj = (int*)(sp + OFF_ADJ);
    float* sInv = (float*)(sp + OFF_INV);
    float* sB   = (float*)(sp + OFF_BIAS);
    float* sG   = (float*)(sp + OFF_GAM);
    float* sBe  = (float*)(sp + OFF_BET);
    float* hS   = (float*)(sp + OFF_H);

    const int tid  = threadIdx.x;
    const int lane = tid & 31;
    const int warp = tid >> 5;               // 8 warps
    const int warp_m = warp & 3;             // 4 in M (16 rows each)
    const int warp_n = warp >> 2;            // 2 in N (64 cols each)
    const int nodeBase = blockIdx.x * TM;
    const float4* X4 = (const float4*)X;

    if (tid < 128) { sB[tid] = bias[tid]; sG[tid] = gamma[tid]; sBe[tid] = beta[tid]; }

    // adjacency -> smem
    for (int i = tid; i < TM * K_NEIGH; i += THREADS) {
        int r = i >> 4;
        int a = -1;
        if (nodeBase + r < N) a = adj[(nodeBase + r) * K_NEIGH + (i & 15)];
        sAdj[i] = a;
    }
    // self features -> A cols [0,128), split hi/lo
    for (int i = tid; i < TM * 32; i += THREADS) {
        int r = i >> 5;
        int c = (i & 31) * 4;
        float4 v = make_float4(0.f, 0.f, 0.f, 0.f);
        if (nodeBase + r < N) v = X4[(nodeBase + r) * 32 + (i & 31)];
        float h0,h1,h2,h3,l0,l1,l2,l3;
        split1(v.x,h0,l0); split1(v.y,h1,l1); split1(v.z,h2,l2); split1(v.w,h3,l3);
        uint32_t off = (uint32_t)r * (A_STRIDE_H * 2) + (uint32_t)c * 2;
        *(uint2*)(sp + OFF_A_HI + off) = make_uint2(pk2(h0,h1), pk2(h2,h3));
        *(uint2*)(sp + OFF_A_LO + off) = make_uint2(pk2(l0,l1), pk2(l2,l3));
    }
    __syncthreads();

    if (tid < TM) {
        int cnt = 0;
        #pragma unroll
        for (int k = 0; k < K_NEIGH; k++) cnt += (sAdj[tid * K_NEIGH + k] >= 0);
        sInv[tid] = 1.0f / (float)(cnt > 1 ? cnt : 1);
    }
    __syncthreads();

    // gather: warp handles 8 nodes; lane covers one float4 column; mean -> A cols [128,256)
    #pragma unroll 1
    for (int ii = 0; ii < 8; ii++) {
        int r = warp * 8 + ii;
        float4 acc4 = make_float4(0.f, 0.f, 0.f, 0.f);
        #pragma unroll
        for (int k = 0; k < K_NEIGH; k++) {
            int j = sAdj[r * K_NEIGH + k];
            if (j >= 0) {
                float4 v = X4[j * 32 + lane];
                acc4.x += v.x; acc4.y += v.y; acc4.z += v.z; acc4.w += v.w;
            }
        }
        float inv = sInv[r];
        acc4.x *= inv; acc4.y *= inv; acc4.z *= inv; acc4.w *= inv;
        float h0,h1,h2,h3,l0,l1,l2,l3;
        split1(acc4.x,h0,l0); split1(acc4.y,h1,l1); split1(acc4.z,h2,l2); split1(acc4.w,h3,l3);
        uint32_t off = (uint32_t)r * (A_STRIDE_H * 2) + (uint32_t)(F_DIM + lane * 4) * 2;
        *(uint2*)(sp + OFF_A_HI + off) = make_uint2(pk2(h0,h1), pk2(h2,h3));
        *(uint2*)(sp + OFF_A_LO + off) = make_uint2(pk2(l0,l1), pk2(l2,l3));
    }

    // per-lane ldmatrix addresses
    const uint32_t aRowByte = (uint32_t)(warp_m * 16 + (lane & 15)) * (A_STRIDE_H * 2)
                            + (uint32_t)(lane >> 4) * 16;
    const uint32_t bRowByte = (uint32_t)(warp_n * 64 + ((lane >> 4) << 3) + (lane & 7)) * (W_STRIDE_H * 2)
                            + (uint32_t)((lane >> 3) & 1) * 16;

    float acc[8][4];
    #pragma unroll
    for (int nt = 0; nt < 8; nt++)
        #pragma unroll
        for (int j = 0; j < 4; j++) acc[nt][j] = 0.f;

    __syncthreads();   // A tiles (incl. gather cols) ready

    #pragma unroll 1
    for (int chunk = 0; chunk < 2; chunk++) {
        #pragma unroll 1
        for (int wsplit = 0; wsplit < 2; wsplit++) {     // 0: Whi, 1: Wlo
            // stage W chunk into single buffer
            const __nv_bfloat16* gw = wsplit ? g_Wlo : g_Whi;
            for (int idx = tid; idx < 128 * 16; idx += THREADS) {
                int o  = idx >> 4;
                int c8 = (idx & 15) * 8;                 // halves
                uint32_t soff = (uint32_t)o * (W_STRIDE_H * 2) + (uint32_t)c8 * 2;
                *(uint4*)(sp + OFF_W + soff) = *(const uint4*)(gw + o * KD + chunk * 128 + c8);
            }
            __syncthreads();

            // asplits: wsplit==0 -> {Ahi, Alo}; wsplit==1 -> {Ahi}
            const int nAs = wsplit ? 1 : 2;
            #pragma unroll 1
            for (int as = 0; as < nAs; as++) {
                const uint32_t aBase = sbase + (as ? OFF_A_LO : OFF_A_HI)
                                     + aRowByte + (uint32_t)chunk * 256;  // chunk*128 halves
                const uint32_t bBase = sbase + OFF_W + bRowByte;
                #pragma unroll
                for (int s = 0; s < 8; s++) {
                    uint32_t a0[4], b[16];
                    ldsm4(a0, aBase + (uint32_t)s * 32);
                    #pragma unroll
                    for (int q = 0; q < 4; q++)
                        ldsm4(b + q * 4, bBase + (uint32_t)q * 16 * (W_STRIDE_H * 2)
                                               + (uint32_t)s * 32);
                    #pragma unroll
                    for (int nt = 0; nt < 8; nt++)
                        mma_bf16(acc[nt], a0, b + nt * 2);
                }
            }
            __syncthreads();   // all ldmatrix done before buffer reuse
        }
    }

    // write h tile to smem (stride 129 floats)
    #pragma unroll
    for (int nt = 0; nt < 8; nt++) {
        int row = warp_m * 16 + (lane >> 2);
        int col = warp_n * 64 + nt * 8 + 2 * (lane & 3);
        hS[row * H_STRIDE + col]           = acc[nt][0];
        hS[row * H_STRIDE + col + 1]       = acc[nt][1];
        hS[(row + 8) * H_STRIDE + col]     = acc[nt][2];
        hS[(row + 8) * H_STRIDE + col + 1] = acc[nt][3];
    }
    __syncthreads();

    // LayerNorm + LeakyReLU: 4 threads per row, 32 cols each, one-pass E[h],E[h^2]
    {
        int row  = tid >> 2;
        int part = tid & 3;
        int cbase = part * 32;
        const float* hrow = hS + row * H_STRIDE + cbase;

        float v[32];
        float s1 = 0.f, s2 = 0.f;
        #pragma unroll
        for (int c = 0; c < 32; c++) {
            float h = hrow[c] + sB[cbase + c];
            v[c] = h;
            s1 += h;
            s2 += h * h;
        }
        s1 += __shfl_xor_sync(0xFFFFFFFFu, s1, 1);
        s2 += __shfl_xor_sync(0xFFFFFFFFu, s2, 1);
        s1 += __shfl_xor_sync(0xFFFFFFFFu, s1, 2);
        s2 += __shfl_xor_sync(0xFFFFFFFFu, s2, 2);
        float mu  = s1 * (1.0f / 128.0f);
        float var = s2 * (1.0f / 128.0f) - mu * mu;
        float rstd = rsqrtf(var + LN_EPS);

        int node = nodeBase + row;
        if (node < N) {
            float* orow = out + (size_t)node * O_DIM + cbase;
            #pragma unroll
            for (int c4 = 0; c4 < 8; c4++) {
                float y[4];
                #pragma unroll
                for (int j = 0; j < 4; j++) {
                    int c = c4 * 4 + j;
                    float t = (v[c] - mu) * rstd * sG[cbase + c] + sBe[cbase + c];
                    y[j] = (t >= 0.f) ? t : NEG_SLOPE * t;
                }
                *(float4*)(orow + c4 * 4) = make_float4(y[0], y[1], y[2], y[3]);
            }
        }
    }
}

extern "C" void kernel_launch(void* const* d_in, const int* in_sizes, int n_in,
                              void* d_out, int out_size)
{
    const float* X     = (const float*)d_in[0];
    const int*   adj   = (const int*)d_in[1];
    const float* W     = (const float*)d_in[2];
    const float* bias  = (const float*)d_in[3];
    const float* gamma = (const float*)d_in[4];
    const float* beta  = (const float*)d_in[5];
    float* out = (float*)d_out;

    int N = in_sizes[0] / F_DIM;

    prep_w_kernel<<<(O_DIM * KD + 255) / 256, 256>>>(W);

    cudaFuncSetAttribute(gnn_mma_kernel,
                         cudaFuncAttributeMaxDynamicSharedMemorySize, SMEM_BYTES);
    int grid = (N + TM - 1) / TM;
    gnn_mma_kernel<<<grid, THREADS, SMEM_BYTES>>>(X, adj, bias, gamma, beta, out, N);
}

// round 6
// speedup vs baseline: 1.7837x; 1.7837x over previous
#include <cuda_runtime.h>
#include <cuda_fp16.h>
#include <cstdint>

#define THREADS   256
#define TM        128
#define F_DIM     128
#define K_NEIGH   16
#define O_DIM     128
#define KD        256
#define NEG_SLOPE 0.2f
#define LN_EPS    1e-5f

// smem layout (bytes). A: 128x256 half, stride 512B, XOR-swizzled (16B units).
// W: 128x128 half, stride 256B, XOR-swizzled.
#define OFF_A      0          // 65536
#define OFF_W      65536      // 32768
#define OFF_ADJ    98304      // 128*16*4 = 8192
#define OFF_INV    106496     // 512
#define OFF_BIAS   107008     // 512
#define OFF_GAM    107520     // 512
#define OFF_BET    108032     // 512
#define SMEM_BYTES 108544
// h tile reuses [0, 67584): 128 rows x 132 f32 stride
#define OFF_H      0
#define H_STRIDE   132

// pre-split W (fp16 hi/lo, row-major [O][KD])
__device__ __half g_Whi[O_DIM * KD];
__device__ __half g_Wlo[O_DIM * KD];

__device__ __forceinline__ uint32_t smem_u32(const void* p) {
    uint32_t a;
    asm("{ .reg .u64 t; cvta.to.shared.u64 t, %1; cvt.u32.u64 %0, t; }" : "=r"(a) : "l"(p));
    return a;
}
__device__ __forceinline__ void ldsm4(uint32_t* r, uint32_t addr) {
    asm volatile("ldmatrix.sync.aligned.m8n8.x4.shared.b16 {%0,%1,%2,%3}, [%4];"
        : "=r"(r[0]), "=r"(r[1]), "=r"(r[2]), "=r"(r[3]) : "r"(addr));
}
__device__ __forceinline__ void mma_f16(float* c, const uint32_t* a, const uint32_t* b) {
    asm volatile("mma.sync.aligned.m16n8k16.row.col.f32.f16.f16.f32 "
        "{%0,%1,%2,%3}, {%4,%5,%6,%7}, {%8,%9}, {%0,%1,%2,%3};"
        : "+f"(c[0]), "+f"(c[1]), "+f"(c[2]), "+f"(c[3])
        : "r"(a[0]), "r"(a[1]), "r"(a[2]), "r"(a[3]), "r"(b[0]), "r"(b[1]));
}
__device__ __forceinline__ uint32_t pkh2(float a, float b) {
    __half2 t = __floats2half2_rn(a, b);
    return *reinterpret_cast<uint32_t*>(&t);
}

// ---------- prep: split W into fp16 hi/lo ----------
__global__ void prep_w_kernel(const float* __restrict__ W) {
    int i = blockIdx.x * blockDim.x + threadIdx.x;
    if (i < O_DIM * KD) {
        float v = W[i];
        __half h = __float2half_rn(v);
        g_Whi[i] = h;
        g_Wlo[i] = __float2half_rn(v - __half2float(h));
    }
}

// ---------- main fused kernel ----------
__global__ void __launch_bounds__(THREADS, 2)
gnn_mma_kernel(const float* __restrict__ X,
               const int* __restrict__ adj,
               const float* __restrict__ bias,
               const float* __restrict__ gamma,
               const float* __restrict__ beta,
               float* __restrict__ out,
               int N)
{
    extern __shared__ __align__(16) char sp[];
    const uint32_t sbase = smem_u32(sp);

    int*   sAdj = (int*)(sp + OFF_ADJ);
    float* sInv = (float*)(sp + OFF_INV);
    float* sB   = (float*)(sp + OFF_BIAS);
    float* sG   = (float*)(sp + OFF_GAM);
    float* sBe  = (float*)(sp + OFF_BET);
    float* hS   = (float*)(sp + OFF_H);

    const int tid  = threadIdx.x;
    const int lane = tid & 31;
    const int warp = tid >> 5;               // 8 warps
    const int warp_m = warp >> 2;            // 2 in M (64 rows each)
    const int warp_n = warp & 3;             // 4 in N (32 cols each)
    const int nodeBase = blockIdx.x * TM;
    const float4* X4 = (const float4*)X;

    if (tid < 128) { sB[tid] = bias[tid]; sG[tid] = gamma[tid]; sBe[tid] = beta[tid]; }

    // adjacency -> smem
    for (int i = tid; i < TM * K_NEIGH; i += THREADS) {
        int r = i >> 4;
        int a = -1;
        if (nodeBase + r < N) a = adj[(nodeBase + r) * K_NEIGH + (i & 15)];
        sAdj[i] = a;
    }
    // self features -> A cols [0,128) fp16, swizzled
    for (int i = tid; i < TM * 32; i += THREADS) {
        int r  = i >> 5;
        int c4 = i & 31;                       // float4 index (4 halves = 8B)
        float4 v = make_float4(0.f, 0.f, 0.f, 0.f);
        if (nodeBase + r < N) v = X4[(nodeBase + r) * 32 + c4];
        uint32_t u = (uint32_t)(c4 >> 1);      // 16B unit along K
        uint32_t off = (uint32_t)r * 512u + ((u ^ (uint32_t)(r & 7)) << 4) + (uint32_t)(c4 & 1) * 8u;
        *(uint2*)(sp + OFF_A + off) = make_uint2(pkh2(v.x, v.y), pkh2(v.z, v.w));
    }
    __syncthreads();

    if (tid < TM) {
        int cnt = 0;
        #pragma unroll
        for (int k = 0; k < K_NEIGH; k++) cnt += (sAdj[tid * K_NEIGH + k] >= 0);
        sInv[tid] = 1.0f / (float)(cnt > 1 ? cnt : 1);
    }
    __syncthreads();

    // gather: warp handles 16 nodes; lane covers one float4 column; mean -> A cols [128,256)
    #pragma unroll 1
    for (int ii = 0; ii < 16; ii++) {
        int r = warp * 16 + ii;
        float4 acc4 = make_float4(0.f, 0.f, 0.f, 0.f);
        #pragma unroll
        for (int k = 0; k < K_NEIGH; k++) {
            int j = sAdj[r * K_NEIGH + k];
            if (j >= 0) {
                float4 v = X4[j * 32 + lane];
                acc4.x += v.x; acc4.y += v.y; acc4.z += v.z; acc4.w += v.w;
            }
        }
        float inv = sInv[r];
        acc4.x *= inv; acc4.y *= inv; acc4.z *= inv; acc4.w *= inv;
        uint32_t u = 16u + (uint32_t)(lane >> 1);
        uint32_t off = (uint32_t)r * 512u + ((u ^ (uint32_t)(r & 7)) << 4) + (uint32_t)(lane & 1) * 8u;
        *(uint2*)(sp + OFF_A + off) = make_uint2(pkh2(acc4.x, acc4.y), pkh2(acc4.z, acc4.w));
    }

    float acc[4][4][4];
    #pragma unroll
    for (int mt = 0; mt < 4; mt++)
        #pragma unroll
        for (int nt = 0; nt < 4; nt++)
            #pragma unroll
            for (int j = 0; j < 4; j++) acc[mt][nt][j] = 0.f;

    // per-lane fixed components
    const int aRow = warp_m * 64 + (lane & 15);          // + mt*16
    const int aSel = lane >> 4;                          // k-unit parity
    const int bN   = warp_n * 32 + ((lane >> 4) << 3) + (lane & 7);  // + q*16
    const int bSel = (lane >> 3) & 1;

    __syncthreads();   // A tile ready

    #pragma unroll 1
    for (int chunk = 0; chunk < 2; chunk++) {
        #pragma unroll 1
        for (int ws = 0; ws < 2; ws++) {                 // 0: Whi, 1: Wlo
            const __half* gw = ws ? g_Wlo : g_Whi;
            for (int idx = tid; idx < 2048; idx += THREADS) {
                int o = idx >> 4, u = idx & 15;
                uint32_t dst = OFF_W + (uint32_t)o * 256u + (((uint32_t)u ^ (uint32_t)(o & 7)) << 4);
                *(uint4*)(sp + dst) = *(const uint4*)(gw + o * KD + chunk * 128 + u * 8);
            }
            __syncthreads();

            #pragma unroll
            for (int s = 0; s < 8; s++) {
                uint32_t a[4][4], b[8];
                #pragma unroll
                for (int mt = 0; mt < 4; mt++) {
                    int row = aRow + mt * 16;
                    uint32_t ku = (uint32_t)(chunk * 16 + s * 2 + aSel);
                    uint32_t addr = sbase + OFF_A + (uint32_t)row * 512u
                                  + ((ku ^ (uint32_t)(row & 7)) << 4);
                    ldsm4(a[mt], addr);
                }
                #pragma unroll
                for (int q = 0; q < 2; q++) {
                    int n = bN + q * 16;
                    uint32_t ku = (uint32_t)(s * 2 + bSel);
                    uint32_t addr = sbase + OFF_W + (uint32_t)n * 256u
                                  + ((ku ^ (uint32_t)(n & 7)) << 4);
                    ldsm4(b + q * 4, addr);
                }
                #pragma unroll
                for (int mt = 0; mt < 4; mt++)
                    #pragma unroll
                    for (int nt = 0; nt < 4; nt++)
                        mma_f16(acc[mt][nt], a[mt], b + nt * 2);
            }
            __syncthreads();   // ldmatrix done before W buffer reuse
        }
    }

    // write h tile to smem (stride 132 floats)
    #pragma unroll
    for (int mt = 0; mt < 4; mt++) {
        int row = warp_m * 64 + mt * 16 + (lane >> 2);
        #pragma unroll
        for (int nt = 0; nt < 4; nt++) {
            int col = warp_n * 32 + nt * 8 + 2 * (lane & 3);
            *(float2*)&hS[row * H_STRIDE + col]       = make_float2(acc[mt][nt][0], acc[mt][nt][1]);
            *(float2*)&hS[(row + 8) * H_STRIDE + col] = make_float2(acc[mt][nt][2], acc[mt][nt][3]);
        }
    }
    __syncthreads();

    // LayerNorm + LeakyReLU: 4 threads/row x 32 cols, 2 row-iterations
    #pragma unroll 1
    for (int iter = 0; iter < 2; iter++) {
        int row   = (tid >> 2) + iter * 64;
        int part  = tid & 3;
        int cbase = part * 32;
        const float* hrow = hS + row * H_STRIDE + cbase;

        float v[32];
        float s1 = 0.f, s2 = 0.f;
        #pragma unroll
        for (int c = 0; c < 32; c++) {
            float h = hrow[c] + sB[cbase + c];
            v[c] = h;
            s1 += h;
            s2 += h * h;
        }
        s1 += __shfl_xor_sync(0xFFFFFFFFu, s1, 1);
        s2 += __shfl_xor_sync(0xFFFFFFFFu, s2, 1);
        s1 += __shfl_xor_sync(0xFFFFFFFFu, s1, 2);
        s2 += __shfl_xor_sync(0xFFFFFFFFu, s2, 2);
        float mu  = s1 * (1.0f / 128.0f);
        float var = s2 * (1.0f / 128.0f) - mu * mu;
        float rstd = rsqrtf(var + LN_EPS);

        int node = nodeBase + row;
        if (node < N) {
            float* orow = out + (size_t)node * O_DIM + cbase;
            #pragma unroll
            for (int c4 = 0; c4 < 8; c4++) {
                float y[4];
                #pragma unroll
                for (int j = 0; j < 4; j++) {
                    int c = c4 * 4 + j;
                    float t = (v[c] - mu) * rstd * sG[cbase + c] + sBe[cbase + c];
                    y[j] = (t >= 0.f) ? t : NEG_SLOPE * t;
                }
                *(float4*)(orow + c4 * 4) = make_float4(y[0], y[1], y[2], y[3]);
            }
        }
    }
}

extern "C" void kernel_launch(void* const* d_in, const int* in_sizes, int n_in,
                              void* d_out, int out_size)
{
    const float* X     = (const float*)d_in[0];
    const int*   adj   = (const int*)d_in[1];
    const float* W     = (const float*)d_in[2];
    const float* bias  = (const float*)d_in[3];
    const float* gamma = (const float*)d_in[4];
    const float* beta  = (const float*)d_in[5];
    float* out = (float*)d_out;

    int N = in_sizes[0] / F_DIM;

    prep_w_kernel<<<(O_DIM * KD + 255) / 256, 256>>>(W);

    cudaFuncSetAttribute(gnn_mma_kernel,
                         cudaFuncAttributeMaxDynamicSharedMemorySize, SMEM_BYTES);
    int grid = (N + TM - 1) / TM;
    gnn_mma_kernel<<<grid, THREADS, SMEM_BYTES>>>(X, adj, bias, gamma, beta, out, N);
}

// round 7
// speedup vs baseline: 1.8049x; 1.0119x over previous
#include <cuda_runtime.h>
#include <cuda_fp16.h>
#include <cstdint>

#define THREADS   256
#define TM        128
#define F_DIM     128
#define K_NEIGH   16
#define O_DIM     128
#define KD        256
#define NEG_SLOPE 0.2f
#define LN_EPS    1e-5f
#define X_MAX_ROWS 131072

// smem layout (bytes). A: 128x256 half, stride 512B, XOR-swizzled (16B units).
// W: 128x128 half, stride 256B, XOR-swizzled.
#define OFF_A      0          // 65536
#define OFF_W      65536      // 32768
#define OFF_ADJ    98304      // 128*16*4 = 8192
#define OFF_INV    106496     // 512
#define OFF_BIAS   107008     // 512
#define OFF_GAM    107520     // 512
#define OFF_BET    108032     // 512
#define SMEM_BYTES 108544
// h tile reuses [0, 67584): 128 rows x 132 f32 stride
#define OFF_H      0
#define H_STRIDE   132

// pre-split W (fp16 hi/lo, row-major [O][KD]) + pre-converted X (fp16)
__device__ __half g_Whi[O_DIM * KD];
__device__ __half g_Wlo[O_DIM * KD];
__device__ __half g_Xh[X_MAX_ROWS * F_DIM];

__device__ __forceinline__ uint32_t smem_u32(const void* p) {
    uint32_t a;
    asm("{ .reg .u64 t; cvta.to.shared.u64 t, %1; cvt.u32.u64 %0, t; }" : "=r"(a) : "l"(p));
    return a;
}
__device__ __forceinline__ void ldsm4(uint32_t* r, uint32_t addr) {
    asm volatile("ldmatrix.sync.aligned.m8n8.x4.shared.b16 {%0,%1,%2,%3}, [%4];"
        : "=r"(r[0]), "=r"(r[1]), "=r"(r[2]), "=r"(r[3]) : "r"(addr));
}
__device__ __forceinline__ void mma_f16(float* c, const uint32_t* a, const uint32_t* b) {
    asm volatile("mma.sync.aligned.m16n8k16.row.col.f32.f16.f16.f32 "
        "{%0,%1,%2,%3}, {%4,%5,%6,%7}, {%8,%9}, {%0,%1,%2,%3};"
        : "+f"(c[0]), "+f"(c[1]), "+f"(c[2]), "+f"(c[3])
        : "r"(a[0]), "r"(a[1]), "r"(a[2]), "r"(a[3]), "r"(b[0]), "r"(b[1]));
}
__device__ __forceinline__ uint32_t pkh2(float a, float b) {
    __half2 t = __floats2half2_rn(a, b);
    return *reinterpret_cast<uint32_t*>(&t);
}

// ---------- prep: split W into fp16 hi/lo ----------
__global__ void prep_w_kernel(const float* __restrict__ W) {
    int i = blockIdx.x * blockDim.x + threadIdx.x;
    if (i < O_DIM * KD) {
        float v = W[i];
        __half h = __float2half_rn(v);
        g_Whi[i] = h;
        g_Wlo[i] = __float2half_rn(v - __half2float(h));
    }
}
// ---------- prep: convert X to fp16 ----------
__global__ void prep_x_kernel(const float* __restrict__ X, int n4) {
    int i = blockIdx.x * blockDim.x + threadIdx.x;   // float4 groups
    if (i < n4) {
        float4 v = ((const float4*)X)[i];
        ((uint2*)g_Xh)[i] = make_uint2(pkh2(v.x, v.y), pkh2(v.z, v.w));
    }
}

// ---------- main fused kernel ----------
__global__ void __launch_bounds__(THREADS, 2)
gnn_mma_kernel(const int* __restrict__ adj,
               const float* __restrict__ bias,
               const float* __restrict__ gamma,
               const float* __restrict__ beta,
               float* __restrict__ out,
               int N)
{
    extern __shared__ __align__(16) char sp[];
    const uint32_t sbase = smem_u32(sp);

    int*   sAdj = (int*)(sp + OFF_ADJ);
    float* sInv = (float*)(sp + OFF_INV);
    float* sB   = (float*)(sp + OFF_BIAS);
    float* sG   = (float*)(sp + OFF_GAM);
    float* sBe  = (float*)(sp + OFF_BET);
    float* hS   = (float*)(sp + OFF_H);

    const int tid  = threadIdx.x;
    const int lane = tid & 31;
    const int warp = tid >> 5;               // 8 warps
    const int warp_m = warp >> 2;            // 2 in M (64 rows each)
    const int warp_n = warp & 3;             // 4 in N (32 cols each)
    const int nodeBase = blockIdx.x * TM;
    const uint2* Xh2 = (const uint2*)g_Xh;   // 8B groups; 32 per row
    const uint4* Xh4 = (const uint4*)g_Xh;   // 16B groups; 16 per row

    if (tid < 128) { sB[tid] = bias[tid]; sG[tid] = gamma[tid]; sBe[tid] = beta[tid]; }

    // adjacency -> smem
    for (int i = tid; i < TM * K_NEIGH; i += THREADS) {
        int r = i >> 4;
        int a = -1;
        if (nodeBase + r < N) a = adj[(nodeBase + r) * K_NEIGH + (i & 15)];
        sAdj[i] = a;
    }
    // self features -> A cols [0,128): straight fp16 copy, swizzled (16B units)
    for (int i = tid; i < TM * 16; i += THREADS) {
        int r = i >> 4;
        int u = i & 15;                        // 16B unit along K (8 halves)
        uint4 v = make_uint4(0u, 0u, 0u, 0u);
        if (nodeBase + r < N) v = Xh4[(nodeBase + r) * 16 + u];
        uint32_t off = (uint32_t)r * 512u + (((uint32_t)u ^ (uint32_t)(r & 7)) << 4);
        *(uint4*)(sp + OFF_A + off) = v;
    }
    __syncthreads();

    if (tid < TM) {
        int cnt = 0;
        #pragma unroll
        for (int k = 0; k < K_NEIGH; k++) cnt += (sAdj[tid * K_NEIGH + k] >= 0);
        sInv[tid] = 1.0f / (float)(cnt > 1 ? cnt : 1);
    }
    __syncthreads();

    // gather (fp16 reads, fp32 accum): warp handles 16 nodes; lane covers 4 halves
    #pragma unroll 1
    for (int ii = 0; ii < 16; ii++) {
        int r = warp * 16 + ii;
        float4 acc4 = make_float4(0.f, 0.f, 0.f, 0.f);
        #pragma unroll
        for (int k = 0; k < K_NEIGH; k++) {
            int j = sAdj[r * K_NEIGH + k];
            if (j >= 0) {
                uint2 v = Xh2[j * 32 + lane];
                float2 f0 = __half22float2(*(__half2*)&v.x);
                float2 f1 = __half22float2(*(__half2*)&v.y);
                acc4.x += f0.x; acc4.y += f0.y; acc4.z += f1.x; acc4.w += f1.y;
            }
        }
        float inv = sInv[r];
        acc4.x *= inv; acc4.y *= inv; acc4.z *= inv; acc4.w *= inv;
        uint32_t u = 16u + (uint32_t)(lane >> 1);
        uint32_t off = (uint32_t)r * 512u + ((u ^ (uint32_t)(r & 7)) << 4) + (uint32_t)(lane & 1) * 8u;
        *(uint2*)(sp + OFF_A + off) = make_uint2(pkh2(acc4.x, acc4.y), pkh2(acc4.z, acc4.w));
    }

    float acc[4][4][4];
    #pragma unroll
    for (int mt = 0; mt < 4; mt++)
        #pragma unroll
        for (int nt = 0; nt < 4; nt++)
            #pragma unroll
            for (int j = 0; j < 4; j++) acc[mt][nt][j] = 0.f;

    // per-lane fixed components
    const int aRow = warp_m * 64 + (lane & 15);          // + mt*16
    const int aSel = lane >> 4;                          // k-unit parity
    const int bN   = warp_n * 32 + ((lane >> 4) << 3) + (lane & 7);  // + q*16
    const int bSel = (lane >> 3) & 1;

    __syncthreads();   // A tile ready

    #pragma unroll 1
    for (int chunk = 0; chunk < 2; chunk++) {
        #pragma unroll 1
        for (int ws = 0; ws < 2; ws++) {                 // 0: Whi, 1: Wlo
            const __half* gw = ws ? g_Wlo : g_Whi;
            for (int idx = tid; idx < 2048; idx += THREADS) {
                int o = idx >> 4, u = idx & 15;
                uint32_t dst = OFF_W + (uint32_t)o * 256u + (((uint32_t)u ^ (uint32_t)(o & 7)) << 4);
                *(uint4*)(sp + dst) = *(const uint4*)(gw + o * KD + chunk * 128 + u * 8);
            }
            __syncthreads();

            #pragma unroll
            for (int s = 0; s < 8; s++) {
                uint32_t a[4][4], b[8];
                #pragma unroll
                for (int mt = 0; mt < 4; mt++) {
                    int row = aRow + mt * 16;
                    uint32_t ku = (uint32_t)(chunk * 16 + s * 2 + aSel);
                    uint32_t addr = sbase + OFF_A + (uint32_t)row * 512u
                                  + ((ku ^ (uint32_t)(row & 7)) << 4);
                    ldsm4(a[mt], addr);
                }
                #pragma unroll
                for (int q = 0; q < 2; q++) {
                    int n = bN + q * 16;
                    uint32_t ku = (uint32_t)(s * 2 + bSel);
                    uint32_t addr = sbase + OFF_W + (uint32_t)n * 256u
                                  + ((ku ^ (uint32_t)(n & 7)) << 4);
                    ldsm4(b + q * 4, addr);
                }
                #pragma unroll
                for (int mt = 0; mt < 4; mt++)
                    #pragma unroll
                    for (int nt = 0; nt < 4; nt++)
                        mma_f16(acc[mt][nt], a[mt], b + nt * 2);
            }
            __syncthreads();   // ldmatrix done before W buffer reuse
        }
    }

    // write h tile to smem (stride 132 floats)
    #pragma unroll
    for (int mt = 0; mt < 4; mt++) {
        int row = warp_m * 64 + mt * 16 + (lane >> 2);
        #pragma unroll
        for (int nt = 0; nt < 4; nt++) {
            int col = warp_n * 32 + nt * 8 + 2 * (lane & 3);
            *(float2*)&hS[row * H_STRIDE + col]       = make_float2(acc[mt][nt][0], acc[mt][nt][1]);
            *(float2*)&hS[(row + 8) * H_STRIDE + col] = make_float2(acc[mt][nt][2], acc[mt][nt][3]);
        }
    }
    __syncthreads();

    // LayerNorm + LeakyReLU: 4 threads/row x 32 cols, 2 row-iterations
    #pragma unroll 1
    for (int iter = 0; iter < 2; iter++) {
        int row   = (tid >> 2) + iter * 64;
        int part  = tid & 3;
        int cbase = part * 32;
        const float* hrow = hS + row * H_STRIDE + cbase;

        float v[32];
        float s1 = 0.f, s2 = 0.f;
        #pragma unroll
        for (int c = 0; c < 32; c++) {
            float h = hrow[c] + sB[cbase + c];
            v[c] = h;
            s1 += h;
            s2 += h * h;
        }
        s1 += __shfl_xor_sync(0xFFFFFFFFu, s1, 1);
        s2 += __shfl_xor_sync(0xFFFFFFFFu, s2, 1);
        s1 += __shfl_xor_sync(0xFFFFFFFFu, s1, 2);
        s2 += __shfl_xor_sync(0xFFFFFFFFu, s2, 2);
        float mu  = s1 * (1.0f / 128.0f);
        float var = s2 * (1.0f / 128.0f) - mu * mu;
        float rstd = rsqrtf(var + LN_EPS);

        int node = nodeBase + row;
        if (node < N) {
            float* orow = out + (size_t)node * O_DIM + cbase;
            #pragma unroll
            for (int c4 = 0; c4 < 8; c4++) {
                float y[4];
                #pragma unroll
                for (int j = 0; j < 4; j++) {
                    int c = c4 * 4 + j;
                    float t = (v[c] - mu) * rstd * sG[cbase + c] + sBe[cbase + c];
                    y[j] = (t >= 0.f) ? t : NEG_SLOPE * t;
                }
                *(float4*)(orow + c4 * 4) = make_float4(y[0], y[1], y[2], y[3]);
            }
        }
    }
}

extern "C" void kernel_launch(void* const* d_in, const int* in_sizes, int n_in,
                              void* d_out, int out_size)
{
    const float* X     = (const float*)d_in[0];
    const int*   adj   = (const int*)d_in[1];
    const float* W     = (const float*)d_in[2];
    const float* bias  = (const float*)d_in[3];
    const float* gamma = (const float*)d_in[4];
    const float* beta  = (const float*)d_in[5];
    float* out = (float*)d_out;

    int N = in_sizes[0] / F_DIM;

    prep_w_kernel<<<(O_DIM * KD + 255) / 256, 256>>>(W);
    int n4 = N * (F_DIM / 4);
    prep_x_kernel<<<(n4 + 255) / 256, 256>>>(X, n4);

    cudaFuncSetAttribute(gnn_mma_kernel,
                         cudaFuncAttributeMaxDynamicSharedMemorySize, SMEM_BYTES);
    int grid = (N + TM - 1) / TM;
    gnn_mma_kernel<<<grid, THREADS, SMEM_BYTES>>>(adj, bias, gamma, beta, out, N);
}

// round 8
// speedup vs baseline: 2.2388x; 1.2404x over previous
#include <cuda_runtime.h>
#include <cuda_fp16.h>
#include <cstdint>

#define THREADS   256
#define TM        128
#define F_DIM     128
#define K_NEIGH   16
#define O_DIM     128
#define KD        256
#define NEG_SLOPE 0.2f
#define LN_EPS    1e-5f
#define X_MAX_ROWS 131072

// smem layout (bytes). A: 128x256 half, stride 512B, XOR-swizzled (16B units).
// W: 128x128 half, stride 256B, XOR-swizzled (single fp16 split).
#define OFF_A      0          // 65536
#define OFF_W      65536      // 32768
#define OFF_ADJ    98304      // 128*16*4 = 8192
#define OFF_INV    106496     // 512
#define OFF_BIAS   107008     // 512
#define OFF_GAM    107520     // 512
#define OFF_BET    108032     // 512
#define SMEM_BYTES 108544
// h tile reuses [0, 67584): 128 rows x 132 f32 stride
#define OFF_H      0
#define H_STRIDE   132

// fp16 W + fp16 X scratch
__device__ __half g_Wh[O_DIM * KD];
__device__ __half g_Xh[X_MAX_ROWS * F_DIM];

__device__ __forceinline__ uint32_t smem_u32(const void* p) {
    uint32_t a;
    asm("{ .reg .u64 t; cvta.to.shared.u64 t, %1; cvt.u32.u64 %0, t; }" : "=r"(a) : "l"(p));
    return a;
}
__device__ __forceinline__ void ldsm4(uint32_t* r, uint32_t addr) {
    asm volatile("ldmatrix.sync.aligned.m8n8.x4.shared.b16 {%0,%1,%2,%3}, [%4];"
        : "=r"(r[0]), "=r"(r[1]), "=r"(r[2]), "=r"(r[3]) : "r"(addr));
}
__device__ __forceinline__ void mma_f16(float* c, const uint32_t* a, const uint32_t* b) {
    asm volatile("mma.sync.aligned.m16n8k16.row.col.f32.f16.f16.f32 "
        "{%0,%1,%2,%3}, {%4,%5,%6,%7}, {%8,%9}, {%0,%1,%2,%3};"
        : "+f"(c[0]), "+f"(c[1]), "+f"(c[2]), "+f"(c[3])
        : "r"(a[0]), "r"(a[1]), "r"(a[2]), "r"(a[3]), "r"(b[0]), "r"(b[1]));
}
__device__ __forceinline__ uint32_t pkh2(float a, float b) {
    __half2 t = __floats2half2_rn(a, b);
    return *reinterpret_cast<uint32_t*>(&t);
}

// ---------- prep: convert W and X to fp16 (one kernel) ----------
__global__ void prep_kernel(const float* __restrict__ X,
                            const float* __restrict__ W, int n4) {
    int i = blockIdx.x * blockDim.x + threadIdx.x;
    if (i < O_DIM * KD) g_Wh[i] = __float2half_rn(W[i]);
    if (i < n4) {
        float4 v = ((const float4*)X)[i];
        ((uint2*)g_Xh)[i] = make_uint2(pkh2(v.x, v.y), pkh2(v.z, v.w));
    }
}

// ---------- main fused kernel ----------
__global__ void __launch_bounds__(THREADS, 2)
gnn_mma_kernel(const int* __restrict__ adj,
               const float* __restrict__ bias,
               const float* __restrict__ gamma,
               const float* __restrict__ beta,
               float* __restrict__ out,
               int N)
{
    extern __shared__ __align__(16) char sp[];
    const uint32_t sbase = smem_u32(sp);

    int*   sAdj = (int*)(sp + OFF_ADJ);
    float* sInv = (float*)(sp + OFF_INV);
    float* sB   = (float*)(sp + OFF_BIAS);
    float* sG   = (float*)(sp + OFF_GAM);
    float* sBe  = (float*)(sp + OFF_BET);
    float* hS   = (float*)(sp + OFF_H);

    const int tid  = threadIdx.x;
    const int lane = tid & 31;
    const int warp = tid >> 5;               // 8 warps
    const int warp_m = warp >> 2;            // 2 in M (64 rows each)
    const int warp_n = warp & 3;             // 4 in N (32 cols each)
    const int nodeBase = blockIdx.x * TM;
    const uint4* Xh4 = (const uint4*)g_Xh;   // 16B groups; 16 per row

    if (tid < 128) { sB[tid] = bias[tid]; sG[tid] = gamma[tid]; sBe[tid] = beta[tid]; }

    // adjacency -> smem
    for (int i = tid; i < TM * K_NEIGH; i += THREADS) {
        int r = i >> 4;
        int a = -1;
        if (nodeBase + r < N) a = adj[(nodeBase + r) * K_NEIGH + (i & 15)];
        sAdj[i] = a;
    }
    // self features -> A cols [0,128): straight fp16 copy, swizzled (16B units)
    for (int i = tid; i < TM * 16; i += THREADS) {
        int r = i >> 4;
        int u = i & 15;                        // 16B unit along K (8 halves)
        uint4 v = make_uint4(0u, 0u, 0u, 0u);
        if (nodeBase + r < N) v = Xh4[(nodeBase + r) * 16 + u];
        uint32_t off = (uint32_t)r * 512u + (((uint32_t)u ^ (uint32_t)(r & 7)) << 4);
        *(uint4*)(sp + OFF_A + off) = v;
    }
    __syncthreads();

    if (tid < TM) {
        int cnt = 0;
        #pragma unroll
        for (int k = 0; k < K_NEIGH; k++) cnt += (sAdj[tid * K_NEIGH + k] >= 0);
        sInv[tid] = 1.0f / (float)(cnt > 1 ? cnt : 1);
    }
    __syncthreads();

    // gather: pair-row scheme. Half-warp covers one full 256B row (16 lanes x 16B).
    // warp handles 16 rows = 8 pairs; r = warp*16 + 2*p + (lane>>4); u = lane&15.
    {
        const int u = lane & 15;
        #pragma unroll 1
        for (int p = 0; p < 8; p++) {
            int r = warp * 16 + 2 * p + (lane >> 4);
            float a0=0.f,a1=0.f,a2=0.f,a3=0.f,a4=0.f,a5=0.f,a6=0.f,a7=0.f;
            #pragma unroll
            for (int k = 0; k < K_NEIGH; k++) {
                int j = sAdj[r * K_NEIGH + k];
                if (j >= 0) {
                    uint4 v = Xh4[j * 16 + u];
                    float2 f;
                    f = __half22float2(*(__half2*)&v.x); a0 += f.x; a1 += f.y;
                    f = __half22float2(*(__half2*)&v.y); a2 += f.x; a3 += f.y;
                    f = __half22float2(*(__half2*)&v.z); a4 += f.x; a5 += f.y;
                    f = __half22float2(*(__half2*)&v.w); a6 += f.x; a7 += f.y;
                }
            }
            float inv = sInv[r];
            uint32_t un = 16u + (uint32_t)u;
            uint32_t off = (uint32_t)r * 512u + ((un ^ (uint32_t)(r & 7)) << 4);
            *(uint4*)(sp + OFF_A + off) = make_uint4(
                pkh2(a0 * inv, a1 * inv), pkh2(a2 * inv, a3 * inv),
                pkh2(a4 * inv, a5 * inv), pkh2(a6 * inv, a7 * inv));
        }
    }

    float acc[4][4][4];
    #pragma unroll
    for (int mt = 0; mt < 4; mt++)
        #pragma unroll
        for (int nt = 0; nt < 4; nt++)
            #pragma unroll
            for (int j = 0; j < 4; j++) acc[mt][nt][j] = 0.f;

    // per-lane fixed components
    const int aRow = warp_m * 64 + (lane & 15);          // + mt*16
    const int aSel = lane >> 4;                          // k-unit parity
    const int bN   = warp_n * 32 + ((lane >> 4) << 3) + (lane & 7);  // + q*16
    const int bSel = (lane >> 3) & 1;

    __syncthreads();   // A tile ready

    #pragma unroll 1
    for (int chunk = 0; chunk < 2; chunk++) {
        // stage fp16 W chunk
        for (int idx = tid; idx < 2048; idx += THREADS) {
            int o = idx >> 4, u = idx & 15;
            uint32_t dst = OFF_W + (uint32_t)o * 256u + (((uint32_t)u ^ (uint32_t)(o & 7)) << 4);
            *(uint4*)(sp + dst) = *(const uint4*)(g_Wh + o * KD + chunk * 128 + u * 8);
        }
        __syncthreads();

        #pragma unroll
        for (int s = 0; s < 8; s++) {
            uint32_t a[4][4], b[8];
            #pragma unroll
            for (int mt = 0; mt < 4; mt++) {
                int row = aRow + mt * 16;
                uint32_t ku = (uint32_t)(chunk * 16 + s * 2 + aSel);
                uint32_t addr = sbase + OFF_A + (uint32_t)row * 512u
                              + ((ku ^ (uint32_t)(row & 7)) << 4);
                ldsm4(a[mt], addr);
            }
            #pragma unroll
            for (int q = 0; q < 2; q++) {
                int n = bN + q * 16;
                uint32_t ku = (uint32_t)(s * 2 + bSel);
                uint32_t addr = sbase + OFF_W + (uint32_t)n * 256u
                              + ((ku ^ (uint32_t)(n & 7)) << 4);
                ldsm4(b + q * 4, addr);
            }
            #pragma unroll
            for (int mt = 0; mt < 4; mt++)
                #pragma unroll
                for (int nt = 0; nt < 4; nt++)
                    mma_f16(acc[mt][nt], a[mt], b + nt * 2);
        }
        __syncthreads();   // ldmatrix done before W buffer reuse
    }

    // write h tile to smem (stride 132 floats)
    #pragma unroll
    for (int mt = 0; mt < 4; mt++) {
        int row = warp_m * 64 + mt * 16 + (lane >> 2);
        #pragma unroll
        for (int nt = 0; nt < 4; nt++) {
            int col = warp_n * 32 + nt * 8 + 2 * (lane & 3);
            *(float2*)&hS[row * H_STRIDE + col]       = make_float2(acc[mt][nt][0], acc[mt][nt][1]);
            *(float2*)&hS[(row + 8) * H_STRIDE + col] = make_float2(acc[mt][nt][2], acc[mt][nt][3]);
        }
    }
    __syncthreads();

    // LayerNorm + LeakyReLU: 4 threads/row x 32 cols, 2 row-iterations
    #pragma unroll 1
    for (int iter = 0; iter < 2; iter++) {
        int row   = (tid >> 2) + iter * 64;
        int part  = tid & 3;
        int cbase = part * 32;
        const float* hrow = hS + row * H_STRIDE + cbase;

        float v[32];
        float s1 = 0.f, s2 = 0.f;
        #pragma unroll
        for (int c = 0; c < 32; c++) {
            float h = hrow[c] + sB[cbase + c];
            v[c] = h;
            s1 += h;
            s2 += h * h;
        }
        s1 += __shfl_xor_sync(0xFFFFFFFFu, s1, 1);
        s2 += __shfl_xor_sync(0xFFFFFFFFu, s2, 1);
        s1 += __shfl_xor_sync(0xFFFFFFFFu, s1, 2);
        s2 += __shfl_xor_sync(0xFFFFFFFFu, s2, 2);
        float mu  = s1 * (1.0f / 128.0f);
        float var = s2 * (1.0f / 128.0f) - mu * mu;
        float rstd = rsqrtf(var + LN_EPS);

        int node = nodeBase + row;
        if (node < N) {
            float* orow = out + (size_t)node * O_DIM + cbase;
            #pragma unroll
            for (int c4 = 0; c4 < 8; c4++) {
                float y[4];
                #pragma unroll
                for (int j = 0; j < 4; j++) {
                    int c = c4 * 4 + j;
                    float t = (v[c] - mu) * rstd * sG[cbase + c] + sBe[cbase + c];
                    y[j] = (t >= 0.f) ? t : NEG_SLOPE * t;
                }
                *(float4*)(orow + c4 * 4) = make_float4(y[0], y[1], y[2], y[3]);
            }
        }
    }
}

extern "C" void kernel_launch(void* const* d_in, const int* in_sizes, int n_in,
                              void* d_out, int out_size)
{
    const float* X     = (const float*)d_in[0];
    const int*   adj   = (const int*)d_in[1];
    const float* W     = (const float*)d_in[2];
    const float* bias  = (const float*)d_in[3];
    const float* gamma = (const float*)d_in[4];
    const float* beta  = (const float*)d_in[5];
    float* out = (float*)d_out;

    int N = in_sizes[0] / F_DIM;
    int n4 = N * (F_DIM / 4);

    prep_kernel<<<(n4 + 255) / 256, 256>>>(X, W, n4);

    cudaFuncSetAttribute(gnn_mma_kernel,
                         cudaFuncAttributeMaxDynamicSharedMemorySize, SMEM_BYTES);
    int grid = (N + TM - 1) / TM;
    gnn_mma_kernel<<<grid, THREADS, SMEM_BYTES>>>(adj, bias, gamma, beta, out, N);
}